// round 14
// baseline (speedup 1.0000x reference)
#include <cuda_runtime.h>
#include <cuda_bf16.h>
#include <cstdint>

#define N 8192
#define BITS 16
#define NLAB 81
#define GAMMA 0.5f
#define ETA 0.5f

#define TILE 128
#define GRID_X (N / TILE)            // 64
#define GRID_Y (N / TILE)            // 64
#define NCTA (GRID_X * GRID_Y)       // 4096
#define NPROLOG (N / 8)              // 1024

// c = 0.5*log2(e): accumulate c*theta so softplus(theta/2) = ln2*log2(1+exp2(c*theta))
#define CSCALE  0.72134752044448170368f
#define LN2F    0.69314718055994530942f
#define TWO_LN2 1.38629436111989061884f
#define SCALE35 2.91038304567337036133e-11f   /* 2^-35 */

typedef unsigned long long u64;

// ---- device scratch ----
__device__ __nv_bfloat16 g_Fb[N * BITS];   // bf16(CSCALE * F)
__device__ __nv_bfloat16 g_Gb[N * BITS];   // bf16(G)
__device__ uint4  g_imgp[N];               // packed labels {b0-31,b32-63,b64-80,0}
__device__ uint4  g_texp[N];
__device__ double g_partial[NCTA];
__device__ double g_partial2[NPROLOG];

__device__ __forceinline__ uint32_t smem_u32(const void* p) {
    uint32_t a;
    asm("{ .reg .u64 t; cvta.to.shared.u64 t, %1; cvt.u32.u64 %0, t; }" : "=r"(a) : "l"(p));
    return a;
}
#define EX2(d, s) asm("ex2.approx.f32 %0, %1;" : "=f"(d) : "f"(s))
#define LG2(d, s) asm("lg2.approx.f32 %0, %1;" : "=f"(d) : "f"(s))

#define LDSM_X4(r0, r1, r2, r3, addr) \
    asm volatile("ldmatrix.sync.aligned.m8n8.x4.shared.b16 {%0,%1,%2,%3}, [%4];" \
                 : "=r"(r0), "=r"(r1), "=r"(r2), "=r"(r3) : "r"(addr))

__device__ __forceinline__ void mma16816(float& d0, float& d1, float& d2, float& d3,
                                         uint32_t a0, uint32_t a1, uint32_t a2, uint32_t a3,
                                         uint32_t b0, uint32_t b1) {
    asm volatile(
        "mma.sync.aligned.m16n8k16.row.col.f32.bf16.bf16.f32 "
        "{%0,%1,%2,%3}, {%4,%5,%6,%7}, {%8,%9}, {%10,%11,%12,%13};"
        : "=f"(d0), "=f"(d1), "=f"(d2), "=f"(d3)
        : "r"(a0), "r"(a1), "r"(a2), "r"(a3), "r"(b0), "r"(b1),
          "f"(0.0f), "f"(0.0f), "f"(0.0f), "f"(0.0f));
}

// ---------------------------------------------------------------------------
// Prolog (R4/R12 exact): one warp per row. Ballot-packs labels, emits
// bf16(c*F), bf16(G), and per-block term2/term3 partials.
// ---------------------------------------------------------------------------
__global__ __launch_bounds__(256)
void prolog_kernel(const int* __restrict__ img, const int* __restrict__ tex,
                   const float* __restrict__ F, const float* __restrict__ G,
                   const float* __restrict__ Bq) {
    const int w    = threadIdx.x >> 5;
    const int lane = threadIdx.x & 31;
    const int row  = blockIdx.x * 8 + w;

    const int* ir = img + (long long)row * NLAB;
    const int* tr = tex + (long long)row * NLAB;
    unsigned i0 = __ballot_sync(0xffffffffu, ir[lane] != 0);
    unsigned i1 = __ballot_sync(0xffffffffu, ir[32 + lane] != 0);
    unsigned i2 = __ballot_sync(0xffffffffu, (lane < NLAB - 64) ? (ir[64 + lane] != 0) : false);
    unsigned t0 = __ballot_sync(0xffffffffu, tr[lane] != 0);
    unsigned t1 = __ballot_sync(0xffffffffu, tr[32 + lane] != 0);
    unsigned t2 = __ballot_sync(0xffffffffu, (lane < NLAB - 64) ? (tr[64 + lane] != 0) : false);
    if (lane == 0) {
        g_imgp[row] = make_uint4(i0, i1, i2, 0u);
        g_texp[row] = make_uint4(t0, t1, t2, 0u);
    }

    float f = 0.0f, g = 0.0f, b = 0.0f;
    if (lane < BITS) {
        f = F[(long long)row * BITS + lane];
        g = G[(long long)row * BITS + lane];
        b = Bq[(long long)row * BITS + lane];
        g_Fb[(long long)row * BITS + lane] = __float2bfloat16_rn(f * CSCALE);
        g_Gb[(long long)row * BITS + lane] = __float2bfloat16_rn(g);
    }
    float df = b - f, dg = b - g;
    float q  = df * df + dg * dg;
    float sf = f, sg = g;
#pragma unroll
    for (int off = 8; off > 0; off >>= 1) {
        q  += __shfl_xor_sync(0xffffffffu, q,  off);
        sf += __shfl_xor_sync(0xffffffffu, sf, off);
        sg += __shfl_xor_sync(0xffffffffu, sg, off);
    }

    __shared__ double wacc[8];
    if (lane == 0)
        wacc[w] = (double)(GAMMA * q + ETA * (sf * sf + sg * sg));
    __syncthreads();
    if (threadIdx.x == 0) {
        double s = 0.0;
#pragma unroll
        for (int i = 0; i < 8; i++) s += wacc[i];
        g_partial2[blockIdx.x] = s;
    }
}

// ---------------------------------------------------------------------------
// Main (R12 champion body; y-split into two launches via ybase so ncu's
// skip-5 capture window lands on a theta launch). Dual accumulators break
// the serial FADD chains.
// ---------------------------------------------------------------------------
__global__ __launch_bounds__(256)
void theta_loss_kernel(int ybase) {
    __shared__ __nv_bfloat16 sA[TILE * BITS];
    __shared__ __nv_bfloat16 sB[TILE * BITS];
    __shared__ uint4 sIlab[TILE];
    __shared__ uint4 sTlab[TILE];
    __shared__ float warp_sum[8];

    const int tid  = threadIdx.x;
    const int wid  = tid >> 5;
    const int lane = tid & 31;
    const int by   = ybase + blockIdx.y;
    const int i0   = by * TILE;
    const int t0   = blockIdx.x * TILE;

    {
        const int r = tid >> 1;
        const int h = (tid & 1) * 8;
        *(uint4*)(sA + r * BITS + h) = *(const uint4*)(g_Fb + (long long)(i0 + r) * BITS + h);
        *(uint4*)(sB + r * BITS + h) = *(const uint4*)(g_Gb + (long long)(t0 + r) * BITS + h);
    }
    if (tid < TILE) sIlab[tid] = g_imgp[i0 + tid];
    else            sTlab[tid - TILE] = g_texp[t0 + (tid - TILE)];
    __syncthreads();

    const int rbase = wid * 16;
    uint32_t a0, a1, a2, a3;
    {
        uint32_t addr = smem_u32(sA) + (uint32_t)((rbase + (lane & 15)) * 32 + ((lane >> 4) << 4));
        LDSM_X4(a0, a1, a2, a3, addr);
    }

    const uint32_t sBu = smem_u32(sB);
    const int qc = (lane & 3) * 2;
    const uint4 il_lo = sIlab[rbase + (lane >> 2)];
    const uint4 il_hi = sIlab[rbase + (lane >> 2) + 8];

    float lsum0 = 0.0f, lsum1 = 0.0f;   // Σ log2(...) - 70/iter, split chains
    float msum0 = 0.0f, msum1 = 0.0f;   // Σ c*theta over sim pairs, split

#pragma unroll
    for (int it = 0; it < 8; it++) {
        const int n0 = it * 16;
        uint32_t b0, b1, b2, b3;
        {
            uint32_t addr = sBu + (uint32_t)((n0 + (lane & 7) + ((lane >> 4) << 3)) * 32
                                             + (((lane >> 3) & 1) << 4));
            LDSM_X4(b0, b1, b2, b3, addr);
        }

        float d0, d1, d2, d3, e0, e1, e2, e3;
        mma16816(d0, d1, d2, d3, a0, a1, a2, a3, b0, b1);
        mma16816(e0, e1, e2, e3, a0, a1, a2, a3, b2, b3);

        // softplus in log2 domain: one lg2 per 8 elements (scaled product)
        float x0, x1, x2, x3, y0, y1, y2, y3;
        EX2(x0, d0); EX2(x1, d1); EX2(x2, d2); EX2(x3, d3);
        EX2(y0, e0); EX2(y1, e1); EX2(y2, e2); EX2(y3, e3);
        float f01 = fmaf(x0, x1, x0 + x1);
        float f23 = fmaf(x2, x3, x2 + x3);
        float qx  = fmaf(f01, f23, f01 + f23) + 1.0f;
        float g01 = fmaf(y0, y1, y0 + y1);
        float g23 = fmaf(y2, y3, y2 + y3);
        float qy  = fmaf(g01, g23, g01 + g23) + 1.0f;
        float prod = (qx * SCALE35) * (qy * SCALE35);   // [2^-70, 2^74]
        float lp;
        LG2(lp, prod);
        if (it & 1) lsum1 += lp; else lsum0 += lp;      // true value - 70

        const uint4 ta = sTlab[n0 + qc];
        const uint4 tb = sTlab[n0 + qc + 1];
        const uint4 tc = sTlab[n0 + qc + 8];
        const uint4 td = sTlab[n0 + qc + 9];

        unsigned m;
        m = (il_lo.x & ta.x) | (il_lo.y & ta.y) | (il_lo.z & ta.z); msum0 += m ? d0 : 0.0f;
        m = (il_lo.x & tb.x) | (il_lo.y & tb.y) | (il_lo.z & tb.z); msum1 += m ? d1 : 0.0f;
        m = (il_hi.x & ta.x) | (il_hi.y & ta.y) | (il_hi.z & ta.z); msum0 += m ? d2 : 0.0f;
        m = (il_hi.x & tb.x) | (il_hi.y & tb.y) | (il_hi.z & tb.z); msum1 += m ? d3 : 0.0f;
        m = (il_lo.x & tc.x) | (il_lo.y & tc.y) | (il_lo.z & tc.z); msum0 += m ? e0 : 0.0f;
        m = (il_lo.x & td.x) | (il_lo.y & td.y) | (il_lo.z & td.z); msum1 += m ? e1 : 0.0f;
        m = (il_hi.x & tc.x) | (il_hi.y & tc.y) | (il_hi.z & tc.z); msum0 += m ? e2 : 0.0f;
        m = (il_hi.x & td.x) | (il_hi.y & td.y) | (il_hi.z & td.z); msum1 += m ? e3 : 0.0f;
    }

    // +560 = 8 iterations * 70 (scale restore)
    float sum = LN2F * ((lsum0 + lsum1) + 560.0f) - TWO_LN2 * (msum0 + msum1);
#pragma unroll
    for (int off = 16; off > 0; off >>= 1)
        sum += __shfl_down_sync(0xffffffffu, sum, off);
    if (lane == 0) warp_sum[wid] = sum;
    __syncthreads();
    if (tid == 0) {
        float s = 0.0f;
#pragma unroll
        for (int w = 0; w < 8; w++) s += warp_sum[w];
        g_partial[by * GRID_X + blockIdx.x] = (double)s;
    }
}

// ---------------------------------------------------------------------------
// Finalize (R4/R12 exact): fixed-order sum of all partials.
// ---------------------------------------------------------------------------
__global__ void finalize_kernel(float* __restrict__ out) {
    __shared__ double sh[256];
    int t = threadIdx.x;
    double acc = 0.0;
    for (int p = t; p < NCTA; p += 256) acc += g_partial[p];
    for (int p = t; p < NPROLOG; p += 256) acc += g_partial2[p];
    sh[t] = acc;
    __syncthreads();
    for (int s = 128; s > 0; s >>= 1) {
        if (t < s) sh[t] += sh[t + s];
        __syncthreads();
    }
    if (t == 0) out[0] = (float)sh[0];
}

// ---------------------------------------------------------------------------
extern "C" void kernel_launch(void* const* d_in, const int* in_sizes, int n_in,
                              void* d_out, int out_size) {
    const float* F = (const float*)d_in[0];
    const float* G = (const float*)d_in[1];
    const float* B = (const float*)d_in[2];
    const int* img = (const int*)d_in[3];
    const int* tex = (const int*)d_in[4];
    float* out = (float*)d_out;

    prolog_kernel<<<NPROLOG, 256>>>(img, tex, F, G, B);

    dim3 half(GRID_X, GRID_Y / 2);
    theta_loss_kernel<<<half, 256>>>(0);
    theta_loss_kernel<<<half, 256>>>(GRID_Y / 2);

    finalize_kernel<<<1, 256>>>(out);
}

// round 15
// speedup vs baseline: 1.0972x; 1.0972x over previous
#include <cuda_runtime.h>
#include <cuda_bf16.h>
#include <cstdint>

#define N 8192
#define BITS 16
#define NLAB 81
#define GAMMA 0.5f
#define ETA 0.5f

#define TILE 128
#define GRID_X (N / TILE)            // 64
#define GRID_Y (N / TILE)            // 64
#define NCTA (GRID_X * GRID_Y)       // 4096
#define NPROLOG (N / 8)              // 1024

// c = 0.5*log2(e): accumulate c*theta so softplus(theta/2) = ln2*log2(1+exp2(c*theta))
#define CSCALE  0.72134752044448170368f
#define LN2F    0.69314718055994530942f
#define TWO_LN2 1.38629436111989061884f
#define SCALE35 2.91038304567337036133e-11f   /* 2^-35 */

typedef unsigned long long u64;

// ---- device scratch ----
__device__ __nv_bfloat16 g_Fb[N * BITS];   // bf16(CSCALE * F)
__device__ __nv_bfloat16 g_Gb[N * BITS];   // bf16(G)
__device__ uint4  g_imgp[N];               // packed labels {b0-31,b32-63,b64-80,0}
__device__ uint4  g_texp[N];
__device__ double g_partial[NCTA];
__device__ double g_partial2[NPROLOG];

__device__ __forceinline__ uint32_t smem_u32(const void* p) {
    uint32_t a;
    asm("{ .reg .u64 t; cvta.to.shared.u64 t, %1; cvt.u32.u64 %0, t; }" : "=r"(a) : "l"(p));
    return a;
}
#define EX2(d, s) asm("ex2.approx.f32 %0, %1;" : "=f"(d) : "f"(s))
#define LG2(d, s) asm("lg2.approx.f32 %0, %1;" : "=f"(d) : "f"(s))

#define LDSM_X4(r0, r1, r2, r3, addr) \
    asm volatile("ldmatrix.sync.aligned.m8n8.x4.shared.b16 {%0,%1,%2,%3}, [%4];" \
                 : "=r"(r0), "=r"(r1), "=r"(r2), "=r"(r3) : "r"(addr))

__device__ __forceinline__ void mma16816(float& d0, float& d1, float& d2, float& d3,
                                         uint32_t a0, uint32_t a1, uint32_t a2, uint32_t a3,
                                         uint32_t b0, uint32_t b1) {
    asm volatile(
        "mma.sync.aligned.m16n8k16.row.col.f32.bf16.bf16.f32 "
        "{%0,%1,%2,%3}, {%4,%5,%6,%7}, {%8,%9}, {%10,%11,%12,%13};"
        : "=f"(d0), "=f"(d1), "=f"(d2), "=f"(d3)
        : "r"(a0), "r"(a1), "r"(a2), "r"(a3), "r"(b0), "r"(b1),
          "f"(0.0f), "f"(0.0f), "f"(0.0f), "f"(0.0f));
}

// ---------------------------------------------------------------------------
// Prolog (R12 exact): one warp per row. Ballot-packs labels, emits bf16(c*F),
// bf16(G), and per-block term2/term3 partials.
// ---------------------------------------------------------------------------
__global__ __launch_bounds__(256)
void prolog_kernel(const int* __restrict__ img, const int* __restrict__ tex,
                   const float* __restrict__ F, const float* __restrict__ G,
                   const float* __restrict__ Bq) {
    const int w    = threadIdx.x >> 5;
    const int lane = threadIdx.x & 31;
    const int row  = blockIdx.x * 8 + w;

    const int* ir = img + (long long)row * NLAB;
    const int* tr = tex + (long long)row * NLAB;
    unsigned i0 = __ballot_sync(0xffffffffu, ir[lane] != 0);
    unsigned i1 = __ballot_sync(0xffffffffu, ir[32 + lane] != 0);
    unsigned i2 = __ballot_sync(0xffffffffu, (lane < NLAB - 64) ? (ir[64 + lane] != 0) : false);
    unsigned t0 = __ballot_sync(0xffffffffu, tr[lane] != 0);
    unsigned t1 = __ballot_sync(0xffffffffu, tr[32 + lane] != 0);
    unsigned t2 = __ballot_sync(0xffffffffu, (lane < NLAB - 64) ? (tr[64 + lane] != 0) : false);
    if (lane == 0) {
        g_imgp[row] = make_uint4(i0, i1, i2, 0u);
        g_texp[row] = make_uint4(t0, t1, t2, 0u);
    }

    float f = 0.0f, g = 0.0f, b = 0.0f;
    if (lane < BITS) {
        f = F[(long long)row * BITS + lane];
        g = G[(long long)row * BITS + lane];
        b = Bq[(long long)row * BITS + lane];
        g_Fb[(long long)row * BITS + lane] = __float2bfloat16_rn(f * CSCALE);
        g_Gb[(long long)row * BITS + lane] = __float2bfloat16_rn(g);
    }
    float df = b - f, dg = b - g;
    float q  = df * df + dg * dg;
    float sf = f, sg = g;
#pragma unroll
    for (int off = 8; off > 0; off >>= 1) {
        q  += __shfl_xor_sync(0xffffffffu, q,  off);
        sf += __shfl_xor_sync(0xffffffffu, sf, off);
        sg += __shfl_xor_sync(0xffffffffu, sg, off);
    }

    __shared__ double wacc[8];
    if (lane == 0)
        wacc[w] = (double)(GAMMA * q + ETA * (sf * sf + sg * sg));
    __syncthreads();
    if (threadIdx.x == 0) {
        double s = 0.0;
#pragma unroll
        for (int i = 0; i < 8; i++) s += wacc[i];
        g_partial2[blockIdx.x] = s;
    }
}

// ---------------------------------------------------------------------------
// Main (R12 exact champion): 128x128 theta tile per CTA via mma.sync bf16;
// softplus in log2 domain, one LG2 per 8 elements; masked-add epilogue.
// ---------------------------------------------------------------------------
__global__ __launch_bounds__(256)
void theta_loss_kernel() {
    __shared__ __nv_bfloat16 sA[TILE * BITS];
    __shared__ __nv_bfloat16 sB[TILE * BITS];
    __shared__ uint4 sIlab[TILE];
    __shared__ uint4 sTlab[TILE];
    __shared__ float warp_sum[8];

    const int tid  = threadIdx.x;
    const int wid  = tid >> 5;
    const int lane = tid & 31;
    const int i0   = blockIdx.y * TILE;
    const int t0   = blockIdx.x * TILE;

    {
        const int r = tid >> 1;
        const int h = (tid & 1) * 8;
        *(uint4*)(sA + r * BITS + h) = *(const uint4*)(g_Fb + (long long)(i0 + r) * BITS + h);
        *(uint4*)(sB + r * BITS + h) = *(const uint4*)(g_Gb + (long long)(t0 + r) * BITS + h);
    }
    if (tid < TILE) sIlab[tid] = g_imgp[i0 + tid];
    else            sTlab[tid - TILE] = g_texp[t0 + (tid - TILE)];
    __syncthreads();

    const int rbase = wid * 16;

    uint32_t a0, a1, a2, a3;
    {
        uint32_t addr = smem_u32(sA) + (uint32_t)((rbase + (lane & 15)) * 32 + ((lane >> 4) << 4));
        LDSM_X4(a0, a1, a2, a3, addr);
    }

    const uint32_t sBu = smem_u32(sB);
    const int qc = (lane & 3) * 2;
    const uint4 il_lo = sIlab[rbase + (lane >> 2)];
    const uint4 il_hi = sIlab[rbase + (lane >> 2) + 8];

    float lsum = 0.0f;   // Σ log2(1+exp2(c*theta)), offset -70/iter
    float msum = 0.0f;   // Σ c*theta over sim pairs

#pragma unroll
    for (int it = 0; it < 8; it++) {
        const int n0 = it * 16;
        uint32_t b0, b1, b2, b3;
        {
            uint32_t addr = sBu + (uint32_t)((n0 + (lane & 7) + ((lane >> 4) << 3)) * 32
                                             + (((lane >> 3) & 1) << 4));
            LDSM_X4(b0, b1, b2, b3, addr);
        }

        float d0, d1, d2, d3, e0, e1, e2, e3;
        mma16816(d0, d1, d2, d3, a0, a1, a2, a3, b0, b1);
        mma16816(e0, e1, e2, e3, a0, a1, a2, a3, b2, b3);

        float x0, x1, x2, x3, y0, y1, y2, y3;
        EX2(x0, d0); EX2(x1, d1); EX2(x2, d2); EX2(x3, d3);
        EX2(y0, e0); EX2(y1, e1); EX2(y2, e2); EX2(y3, e3);
        float f01 = fmaf(x0, x1, x0 + x1);
        float f23 = fmaf(x2, x3, x2 + x3);
        float qx  = fmaf(f01, f23, f01 + f23) + 1.0f;
        float g01 = fmaf(y0, y1, y0 + y1);
        float g23 = fmaf(y2, y3, y2 + y3);
        float qy  = fmaf(g01, g23, g01 + g23) + 1.0f;
        float prod = (qx * SCALE35) * (qy * SCALE35);   // [2^-70, 2^74]
        float lp;
        LG2(lp, prod);
        lsum += lp;                                      // true value - 70

        const uint4 ta = sTlab[n0 + qc];
        const uint4 tb = sTlab[n0 + qc + 1];
        const uint4 tc = sTlab[n0 + qc + 8];
        const uint4 td = sTlab[n0 + qc + 9];

        unsigned m;
        m = (il_lo.x & ta.x) | (il_lo.y & ta.y) | (il_lo.z & ta.z); msum += m ? d0 : 0.0f;
        m = (il_lo.x & tb.x) | (il_lo.y & tb.y) | (il_lo.z & tb.z); msum += m ? d1 : 0.0f;
        m = (il_hi.x & ta.x) | (il_hi.y & ta.y) | (il_hi.z & ta.z); msum += m ? d2 : 0.0f;
        m = (il_hi.x & tb.x) | (il_hi.y & tb.y) | (il_hi.z & tb.z); msum += m ? d3 : 0.0f;
        m = (il_lo.x & tc.x) | (il_lo.y & tc.y) | (il_lo.z & tc.z); msum += m ? e0 : 0.0f;
        m = (il_lo.x & td.x) | (il_lo.y & td.y) | (il_lo.z & td.z); msum += m ? e1 : 0.0f;
        m = (il_hi.x & tc.x) | (il_hi.y & tc.y) | (il_hi.z & tc.z); msum += m ? e2 : 0.0f;
        m = (il_hi.x & td.x) | (il_hi.y & td.y) | (il_hi.z & td.z); msum += m ? e3 : 0.0f;
    }

    // +560 = 8 iterations * 70 (scale restore)
    float sum = LN2F * (lsum + 560.0f) - TWO_LN2 * msum;
#pragma unroll
    for (int off = 16; off > 0; off >>= 1)
        sum += __shfl_down_sync(0xffffffffu, sum, off);
    if (lane == 0) warp_sum[wid] = sum;
    __syncthreads();
    if (tid == 0) {
        float s = 0.0f;
#pragma unroll
        for (int w = 0; w < 8; w++) s += warp_sum[w];
        g_partial[blockIdx.y * gridDim.x + blockIdx.x] = (double)s;
    }
}

// ---------------------------------------------------------------------------
// Finalize (MLP-FIXED): 1024 threads; each thread issues its 4+1 loads into
// INDEPENDENT accumulators (all in flight at once) instead of a 20-deep
// serial load->add chain. Fixed-order deterministic tree reduction.
// Was 14.8us (28% of runtime!) at MLP=1; now one memory round-trip.
// ---------------------------------------------------------------------------
__global__ __launch_bounds__(1024)
void finalize_kernel(float* __restrict__ out) {
    __shared__ double sh[1024];
    const int t = threadIdx.x;

    // NCTA = 4096 = 4 * 1024 ; NPROLOG = 1024
    double a0 = g_partial[t];
    double a1 = g_partial[t + 1024];
    double a2 = g_partial[t + 2048];
    double a3 = g_partial[t + 3072];
    double a4 = g_partial2[t];
    sh[t] = ((a0 + a1) + (a2 + a3)) + a4;
    __syncthreads();

    for (int s = 512; s > 0; s >>= 1) {
        if (t < s) sh[t] += sh[t + s];
        __syncthreads();
    }
    if (t == 0) out[0] = (float)sh[0];
}

// ---------------------------------------------------------------------------
extern "C" void kernel_launch(void* const* d_in, const int* in_sizes, int n_in,
                              void* d_out, int out_size) {
    const float* F = (const float*)d_in[0];
    const float* G = (const float*)d_in[1];
    const float* B = (const float*)d_in[2];
    const int* img = (const int*)d_in[3];
    const int* tex = (const int*)d_in[4];
    float* out = (float*)d_out;

    prolog_kernel<<<NPROLOG, 256>>>(img, tex, F, G, B);

    dim3 grid(GRID_X, GRID_Y);
    theta_loss_kernel<<<grid, 256>>>();

    finalize_kernel<<<1, 1024>>>(out);
}